// round 8
// baseline (speedup 1.0000x reference)
#include <cuda_runtime.h>

// Patch2Im / fold (col2im) with averaging and crop.
// Input : x_patch [B=4, C=64, K=7, K=7, NH=85, NW=85] fp32 (row-major)
// Output: [B, C, 253, 253] fp32 (padded frame 259x259, crop 3 each side)
//
// v3: cooperative aligned-float4 staging.
// Each block = one (output row h, fused batch*channel bc). Its entire read
// set is ni*7 contiguous ranges of 85 floats (ni = 2 or 3 valid kernel-row
// planes). Phase 1 loads each range as 22 ALIGNED LDG.128 into smem
// (every request 4/4 sectors). Phase 2: 85 compute lanes gather their
// (+1/0/-1)-shifted values from smem, normalize with analytic counts
// (selected reciprocal constants), stage the 253-float row, store coalesced.

namespace {
constexpr int K     = 7;
constexpr int NH    = 85;
constexpr int NW    = 85;
constexpr int PLANE = NH * NW;               // 7225
constexpr int PAD   = 3;
constexpr int HO    = 253;
constexpr int WO    = 253;
constexpr int BC    = 4 * 64;
constexpr long long SLAB  = (long long)K * K * PLANE;   // 354025 (== 1 mod 4)
constexpr long long TOTAL = (long long)BC * SLAB;       // 90630400 floats
constexpr int TPB   = 128;
constexpr int MAXR  = 21;                    // max ranges (3 planes * 7)
constexpr int RW    = 88;                    // smem floats per range (22 f4)
}

__global__ __launch_bounds__(TPB)
void patch2im_kernel(const float* __restrict__ xp, float* __restrict__ out)
{
    __shared__ float sm[MAXR * RW];          // staged input ranges (7.4 KB)
    __shared__ float srow[NW * 3];           // staged output row (255 slots)

    const int h   = blockIdx.x;              // 0..252
    const int bc  = blockIdx.y;              // 0..255
    const int tid = threadIdx.x;             // 0..127
    const int oh  = h + PAD;                 // 3..255

    // Valid kernel-row plane offsets (uniform per block). ni is 2 or 3.
    int offi[3];
    int ni = 0;
    const int ri = oh % 3;
    #pragma unroll
    for (int s = 0; s < 3; ++s) {
        const int i = ri + 3 * s;
        if (i < K) {
            const int d = oh - i;
            if (d >= 0) {
                const int ph = d / 3;
                if (ph < NH) offi[ni++] = i * (K * PLANE) + ph * NW;
            }
        }
    }
    const int nr = 7 * ni;                   // 14 or 21 ranges

    const long long base = (long long)bc * SLAB;

    // ---------------- Phase 1: aligned float4 staging ----------------
    // Range r = (a = r/7, jj = r%7). s_r = offi[a] + jj*PLANE + shift[jj],
    // shift = +1 (jj<3), 0 (jj<6), -1 (jj=6). Elements s_r + t, t in [0,84].
    // Chunk v covers global floats (g & ~3) + 4v .. +3, v = 0..21.
    const int nchunk = nr * 22;
    for (int idx = tid; idx < nchunk; idx += TPB) {
        const int r  = idx / 22;
        const int v  = idx - r * 22;
        const int a  = r / 7;
        const int jj = r - a * 7;
        const int shift = (jj < 3) ? 1 : ((jj < 6) ? 0 : -1);
        const long long g = base + offi[a] + jj * PLANE + shift;
        const long long p = (g & ~3LL) + 4 * v;
        float4 f;
        if (p + 3 < TOTAL) {
            f = __ldcs(reinterpret_cast<const float4*>(xp + p));
        } else {                              // only the tail of the last slab
            f.x = (p + 0 < TOTAL) ? xp[p + 0] : 0.f;
            f.y = (p + 1 < TOTAL) ? xp[p + 1] : 0.f;
            f.z = (p + 2 < TOTAL) ? xp[p + 2] : 0.f;
            f.w = 0.f;
        }
        *reinterpret_cast<float4*>(&sm[r * RW + 4 * v]) = f;
    }
    __syncthreads();

    // ---------------- Phase 2: gather, normalize, stage row ----------------
    if (tid < NW) {
        const int t = tid;                   // column group 0..84
        const bool p012 = (t <= NW - 2);     // +1 shift in range (jj 0..2)
        const bool p6   = (t >= 1);          // -1 shift in range (jj 6)

        float a0 = 0.f, a1 = 0.f, a2 = 0.f;

        #pragma unroll
        for (int a = 0; a < 3; ++a) {
            if (a < ni) {                    // uniform branch
                #pragma unroll
                for (int jj = 0; jj < 7; ++jj) {
                    const int shift = (jj < 3) ? 1 : ((jj < 6) ? 0 : -1);
                    const int s_r = offi[a] + jj * PLANE + shift;
                    // global alignment: SLAB % 4 == 1 -> (bc*SLAB+s_r)&3 = (bc+s_r)&3
                    const int d = (bc + s_r) & 3;
                    const int r = a * 7 + jj;
                    const float v = sm[r * RW + d + t];
                    const bool ok = (jj < 3) ? p012 : ((jj < 6) ? true : p6);
                    if (ok) {
                        const int e = jj % 3;
                        if      (e == 0) a0 += v;
                        else if (e == 1) a1 += v;
                        else             a2 += v;
                    }
                }
            }
        }

        // Analytic normalization (counts are ni * nj, nj from predicates).
        float inv0, inv12;
        if (ni == 3) {
            inv0  = (p012 && p6) ? (1.f / 9.f) : (1.f / 6.f);
            inv12 = p012 ? (1.f / 6.f) : (1.f / 3.f);
        } else {
            inv0  = (p012 && p6) ? (1.f / 6.f) : (1.f / 4.f);
            inv12 = p012 ? (1.f / 4.f) : (1.f / 2.f);
        }
        srow[3 * t + 0] = a0 * inv0;
        srow[3 * t + 1] = a1 * inv12;
        srow[3 * t + 2] = a2 * inv12;
    }
    __syncthreads();

    // ---------------- Phase 3: coalesced row store ----------------
    float* __restrict__ orow = out + ((size_t)bc * HO + h) * WO;
    #pragma unroll
    for (int i = 0; i < 2; ++i) {
        const int w = tid + i * TPB;
        if (w < WO) orow[w] = srow[w];
    }
}

extern "C" void kernel_launch(void* const* d_in, const int* in_sizes, int n_in,
                              void* d_out, int out_size)
{
    (void)in_sizes; (void)n_in; (void)out_size;
    const float* xp = (const float*)d_in[0];
    float* out = (float*)d_out;

    dim3 grid(HO, BC);   // 253 x 256
    dim3 block(TPB);
    patch2im_kernel<<<grid, block>>>(xp, out);
}

// round 9
// speedup vs baseline: 1.0097x; 1.0097x over previous
#include <cuda_runtime.h>

// Patch2Im / fold (col2im) with averaging and crop.
// Input : x_patch [B=4, C=64, K=7, K=7, NH=85, NW=85] fp32 (row-major)
// Output: [B, C, 253, 253] fp32 (padded frame 259x259, crop 3 each side)
//
// v3: cooperative aligned-float4 staging.
// Each block = one (output row h, fused batch*channel bc). Its entire read
// set is ni*7 contiguous ranges of 85 floats (ni = 2 or 3 valid kernel-row
// planes). Phase 1 loads each range as 22 ALIGNED LDG.128 into smem
// (every request 4/4 sectors). Phase 2: 85 compute lanes gather their
// (+1/0/-1)-shifted values from smem, normalize with analytic counts
// (selected reciprocal constants), stage the 253-float row, store coalesced.

namespace {
constexpr int K     = 7;
constexpr int NH    = 85;
constexpr int NW    = 85;
constexpr int PLANE = NH * NW;               // 7225
constexpr int PAD   = 3;
constexpr int HO    = 253;
constexpr int WO    = 253;
constexpr int BC    = 4 * 64;
constexpr long long SLAB  = (long long)K * K * PLANE;   // 354025 (== 1 mod 4)
constexpr long long TOTAL = (long long)BC * SLAB;       // 90630400 floats
constexpr int TPB   = 128;
constexpr int MAXR  = 21;                    // max ranges (3 planes * 7)
constexpr int RW    = 88;                    // smem floats per range (22 f4)
}

__global__ __launch_bounds__(TPB)
void patch2im_kernel(const float* __restrict__ xp, float* __restrict__ out)
{
    __shared__ float sm[MAXR * RW];          // staged input ranges (7.4 KB)
    __shared__ float srow[NW * 3];           // staged output row (255 slots)

    const int h   = blockIdx.x;              // 0..252
    const int bc  = blockIdx.y;              // 0..255
    const int tid = threadIdx.x;             // 0..127
    const int oh  = h + PAD;                 // 3..255

    // Valid kernel-row plane offsets (uniform per block). ni is 2 or 3.
    int offi[3];
    int ni = 0;
    const int ri = oh % 3;
    #pragma unroll
    for (int s = 0; s < 3; ++s) {
        const int i = ri + 3 * s;
        if (i < K) {
            const int d = oh - i;
            if (d >= 0) {
                const int ph = d / 3;
                if (ph < NH) offi[ni++] = i * (K * PLANE) + ph * NW;
            }
        }
    }
    const int nr = 7 * ni;                   // 14 or 21 ranges

    const long long base = (long long)bc * SLAB;

    // ---------------- Phase 1: aligned float4 staging ----------------
    // Range r = (a = r/7, jj = r%7). s_r = offi[a] + jj*PLANE + shift[jj],
    // shift = +1 (jj<3), 0 (jj<6), -1 (jj=6). Elements s_r + t, t in [0,84].
    // Chunk v covers global floats (g & ~3) + 4v .. +3, v = 0..21.
    const int nchunk = nr * 22;
    for (int idx = tid; idx < nchunk; idx += TPB) {
        const int r  = idx / 22;
        const int v  = idx - r * 22;
        const int a  = r / 7;
        const int jj = r - a * 7;
        const int shift = (jj < 3) ? 1 : ((jj < 6) ? 0 : -1);
        const long long g = base + offi[a] + jj * PLANE + shift;
        const long long p = (g & ~3LL) + 4 * v;
        float4 f;
        if (p + 3 < TOTAL) {
            f = __ldcs(reinterpret_cast<const float4*>(xp + p));
        } else {                              // only the tail of the last slab
            f.x = (p + 0 < TOTAL) ? xp[p + 0] : 0.f;
            f.y = (p + 1 < TOTAL) ? xp[p + 1] : 0.f;
            f.z = (p + 2 < TOTAL) ? xp[p + 2] : 0.f;
            f.w = 0.f;
        }
        *reinterpret_cast<float4*>(&sm[r * RW + 4 * v]) = f;
    }
    __syncthreads();

    // ---------------- Phase 2: gather, normalize, stage row ----------------
    if (tid < NW) {
        const int t = tid;                   // column group 0..84
        const bool p012 = (t <= NW - 2);     // +1 shift in range (jj 0..2)
        const bool p6   = (t >= 1);          // -1 shift in range (jj 6)

        float a0 = 0.f, a1 = 0.f, a2 = 0.f;

        #pragma unroll
        for (int a = 0; a < 3; ++a) {
            if (a < ni) {                    // uniform branch
                #pragma unroll
                for (int jj = 0; jj < 7; ++jj) {
                    const int shift = (jj < 3) ? 1 : ((jj < 6) ? 0 : -1);
                    const int s_r = offi[a] + jj * PLANE + shift;
                    // global alignment: SLAB % 4 == 1 -> (bc*SLAB+s_r)&3 = (bc+s_r)&3
                    const int d = (bc + s_r) & 3;
                    const int r = a * 7 + jj;
                    const float v = sm[r * RW + d + t];
                    const bool ok = (jj < 3) ? p012 : ((jj < 6) ? true : p6);
                    if (ok) {
                        const int e = jj % 3;
                        if      (e == 0) a0 += v;
                        else if (e == 1) a1 += v;
                        else             a2 += v;
                    }
                }
            }
        }

        // Analytic normalization (counts are ni * nj, nj from predicates).
        float inv0, inv12;
        if (ni == 3) {
            inv0  = (p012 && p6) ? (1.f / 9.f) : (1.f / 6.f);
            inv12 = p012 ? (1.f / 6.f) : (1.f / 3.f);
        } else {
            inv0  = (p012 && p6) ? (1.f / 6.f) : (1.f / 4.f);
            inv12 = p012 ? (1.f / 4.f) : (1.f / 2.f);
        }
        srow[3 * t + 0] = a0 * inv0;
        srow[3 * t + 1] = a1 * inv12;
        srow[3 * t + 2] = a2 * inv12;
    }
    __syncthreads();

    // ---------------- Phase 3: coalesced row store ----------------
    float* __restrict__ orow = out + ((size_t)bc * HO + h) * WO;
    #pragma unroll
    for (int i = 0; i < 2; ++i) {
        const int w = tid + i * TPB;
        if (w < WO) orow[w] = srow[w];
    }
}

extern "C" void kernel_launch(void* const* d_in, const int* in_sizes, int n_in,
                              void* d_out, int out_size)
{
    (void)in_sizes; (void)n_in; (void)out_size;
    const float* xp = (const float*)d_in[0];
    float* out = (float*)d_out;

    dim3 grid(HO, BC);   // 253 x 256
    dim3 block(TPB);
    patch2im_kernel<<<grid, block>>>(xp, out);
}